// round 16
// baseline (speedup 1.0000x reference)
#include <cuda_runtime.h>
#include <cstdint>

#define NN      50000
#define NE      800000
#define MROWS   100000      // B*N rows
#define EPS_BN  1e-5f
#define SCAN_NB 196         // ceil(NN/256)
#define GB      782         // ceil(MROWS/128) gemm tiles
#define GB2     391         // first-half gemm tiles
#define EB      3125        // ceil(NE/256) edge blocks

// ---------------- scratch (device globals; no allocation allowed) ----------------
__device__ float g_buf1[(size_t)MROWS * 64];   // gemm1 out, then fused-layer2 output h2
__device__ float g_buf2[(size_t)MROWS * 64];   // z1 = post-agg1 ReLU features
__device__ float g_deg[NN];
__device__ float g_dinv[NN];
__device__ int   g_cnt[NN];
__device__ int   g_cur[NN];
__device__ int   g_rowptr[NN + 1];
__device__ int   g_csr_src[NE];
__device__ float g_csr_norm[NE];
__device__ float g_ew[NE];                     // exp(edge_weight), computed once
__device__ float g_bn[4 * 64];                 // [sum1 | sq1 | sum2 | sq2]
__device__ float g_W2p[64 * 64];               // diag(s1) @ W2
__device__ float g_c2[64];                     // t1 @ W2
__device__ int   g_is64;                       // edge_index dtype flag
__device__ int   g_pk[SCAN_NB];                // lookback state: (incl_or_agg<<2)|flag

__device__ __forceinline__ int edge_at(const void* ei, long long idx) {
    if (g_is64) return (int)((const long long*)ei)[idx];
    return ((const int*)ei)[idx];
}

// ---------------- init (+ dtype detect folded in) ----------------
__global__ void k_init(const int* __restrict__ p) {
    int i = blockIdx.x * blockDim.x + threadIdx.x;
    if (i < NN) { g_cnt[i] = 0; g_deg[i] = 1.0f; }   // self-loop weight 1
    if (i < 256) g_bn[i] = 0.f;
    if (i < SCAN_NB) g_pk[i] = 0;
    if (i == 0) {
        int ornz = 0;
        #pragma unroll
        for (int q = 1; q < 32; q += 2) ornz |= p[q];
        g_is64 = (ornz == 0) ? 1 : 0;
    }
}

// ---------------- device pieces for fat kernels ----------------
__device__ __forceinline__ void deg_dev(int chunk, const void* __restrict__ ei,
                                        const float* __restrict__ ew) {
    int e = chunk * 256 + threadIdx.x;
    if (e >= NE) return;
    int c = edge_at(ei, (long long)NE + e);
    float w = expf(ew[e]);
    g_ew[e] = w;
    atomicAdd(&g_deg[c], w);
    atomicAdd(&g_cnt[c], 1);
}

__device__ __forceinline__ void fill_dev(int chunk, const void* __restrict__ ei) {
    int e = chunk * 256 + threadIdx.x;
    if (e >= NE) return;
    int r = edge_at(ei, e);
    int c = edge_at(ei, (long long)NE + e);
    float w = g_ew[e];
    int pos = atomicAdd(&g_cur[c], 1);
    g_csr_src[pos]  = r;
    g_csr_norm[pos] = g_dinv[r] * w * g_dinv[c];
}

// ---------------- scalar SGEMM tile (layer 1), double-buffered smem ----------------
__device__ __forceinline__ void gemm_dev(int tile, const float* __restrict__ Aarg,
                                         const float* __restrict__ Barg) {
    const int K = 128;
    __shared__ __align__(16) float As[2][16][132];
    __shared__ __align__(16) float Bs[2][16][68];
    const float* A  = Aarg;
    const float* Bm = Barg;
    float* C = g_buf1;

    const int tid  = threadIdx.x;
    const int bm   = tile * 128;
    const int tn   = (tid & 15) * 4;   // 0..60
    const int tm   = (tid >> 4) * 8;   // 0..120
    const int arow = tid >> 1;         // 0..127
    const int akq  = (tid & 1) * 8;    // 0 or 8
    const int bk   = tid >> 4;         // 0..15
    const int bj   = (tid & 15) * 4;   // 0..60

    float acc[8][4];
    #pragma unroll
    for (int i = 0; i < 8; i++)
        #pragma unroll
        for (int j = 0; j < 4; j++) acc[i][j] = 0.f;

    const int gr = bm + arow;
    const bool grok = (gr < MROWS);
    const float* Arow = A + (size_t)(grok ? gr : 0) * K;

    const float4 z4 = make_float4(0.f, 0.f, 0.f, 0.f);
    float4 av0 = grok ? *(const float4*)(Arow + akq)     : z4;
    float4 av1 = grok ? *(const float4*)(Arow + akq + 4) : z4;
    float4 bv  = *(const float4*)(Bm + (size_t)bk * 64 + bj);

    As[0][akq + 0][arow] = av0.x; As[0][akq + 1][arow] = av0.y;
    As[0][akq + 2][arow] = av0.z; As[0][akq + 3][arow] = av0.w;
    As[0][akq + 4][arow] = av1.x; As[0][akq + 5][arow] = av1.y;
    As[0][akq + 6][arow] = av1.z; As[0][akq + 7][arow] = av1.w;
    *(float4*)&Bs[0][bk][bj] = bv;
    __syncthreads();

    const int NC = K / 16;
    for (int c = 0; c < NC; c++) {
        const int cur = c & 1;
        if (c + 1 < NC) {
            av0 = grok ? *(const float4*)(Arow + (c + 1) * 16 + akq)     : z4;
            av1 = grok ? *(const float4*)(Arow + (c + 1) * 16 + akq + 4) : z4;
            bv  = *(const float4*)(Bm + (size_t)((c + 1) * 16 + bk) * 64 + bj);
        }
        #pragma unroll
        for (int kk = 0; kk < 16; kk++) {
            float4 a0 = *(const float4*)&As[cur][kk][tm];
            float4 a1 = *(const float4*)&As[cur][kk][tm + 4];
            float4 bb = *(const float4*)&Bs[cur][kk][tn];
            float a[8] = {a0.x, a0.y, a0.z, a0.w, a1.x, a1.y, a1.z, a1.w};
            float b[4] = {bb.x, bb.y, bb.z, bb.w};
            #pragma unroll
            for (int i = 0; i < 8; i++)
                #pragma unroll
                for (int j = 0; j < 4; j++)
                    acc[i][j] = fmaf(a[i], b[j], acc[i][j]);
        }
        if (c + 1 < NC) {
            const int nxt = 1 - cur;
            As[nxt][akq + 0][arow] = av0.x; As[nxt][akq + 1][arow] = av0.y;
            As[nxt][akq + 2][arow] = av0.z; As[nxt][akq + 3][arow] = av0.w;
            As[nxt][akq + 4][arow] = av1.x; As[nxt][akq + 5][arow] = av1.y;
            As[nxt][akq + 6][arow] = av1.z; As[nxt][akq + 7][arow] = av1.w;
            *(float4*)&Bs[nxt][bk][bj] = bv;
            __syncthreads();
        }
    }

    #pragma unroll
    for (int i = 0; i < 8; i++) {
        int m = bm + tm + i;
        if (m < MROWS) {
            int b = m / NN; int n = m - b * NN; int dst = n * 2 + b;
            *(float4*)(C + (size_t)dst * 64 + tn) =
                make_float4(acc[i][0], acc[i][1], acc[i][2], acc[i][3]);
        }
    }
}

// ---------------- fat kernels: overlap gemm1 halves with deg / fill ----------------
__global__ __launch_bounds__(256) void k_fat1(const float* __restrict__ x,
                                              const float* __restrict__ W1,
                                              const void* __restrict__ ei,
                                              const float* __restrict__ ew) {
    if (blockIdx.x < GB2) gemm_dev(blockIdx.x, x, W1);
    else                  deg_dev(blockIdx.x - GB2, ei, ew);
}

__global__ __launch_bounds__(256) void k_fat2(const float* __restrict__ x,
                                              const float* __restrict__ W1,
                                              const void* __restrict__ ei) {
    if (blockIdx.x < (GB - GB2)) gemm_dev(GB2 + blockIdx.x, x, W1);
    else                         fill_dev(blockIdx.x - (GB - GB2), ei);
}

// ---------------- single-pass scan with warp-parallel decoupled lookback ----------------
__device__ __forceinline__ int block_incl_scan(int v, int tid) {
    __shared__ int ws[8];
    int lane = tid & 31, wid = tid >> 5;
    int x = v;
    #pragma unroll
    for (int off = 1; off < 32; off <<= 1) {
        int y = __shfl_up_sync(0xffffffffu, x, off);
        if (lane >= off) x += y;
    }
    if (lane == 31) ws[wid] = x;
    __syncthreads();
    if (wid == 0) {
        int wv = (lane < 8) ? ws[lane] : 0;
        int wx = wv;
        #pragma unroll
        for (int off = 1; off < 8; off <<= 1) {
            int y = __shfl_up_sync(0xffffffffu, wx, off);
            if (lane >= off) wx += y;
        }
        if (lane < 8) ws[lane] = wx - wv;     // exclusive warp prefix
    }
    __syncthreads();
    return x + ws[wid];
}

__global__ __launch_bounds__(256) void k_scan1() {
    const int tid = threadIdx.x, b = blockIdx.x;
    const int lane = tid & 31, wid = tid >> 5;
    int i = b * 256 + tid;
    int v = (i < NN) ? g_cnt[i] : 0;
    int incl = block_incl_scan(v, tid);
    __shared__ int s_base;
    if (wid == 7) {
        int S_b = __shfl_sync(0xffffffffu, incl, 31);   // block total
        if (lane == 31) {
            int flag = (b == 0) ? 2 : 1;
            atomicExch(&g_pk[b], (S_b << 2) | flag);
        }
        int run = 0;
        if (b > 0) {
            int base = b - 1;
            while (true) {
                int j = base - lane;
                bool act = (j >= 0);
                int w = act ? atomicAdd(&g_pk[j], 0) : 0;
                while (__any_sync(0xffffffffu, act && (w & 3) == 0)) {
                    if (act && (w & 3) == 0) w = atomicAdd(&g_pk[j], 0);
                }
                int f   = act ? (w & 3) : 0;
                int val = w >> 2;
                unsigned has2 = __ballot_sync(0xffffffffu, act && f == 2);
                int l2 = has2 ? (__ffs(has2) - 1) : 31;
                int part = (act && lane <= l2) ? val : 0;
                #pragma unroll
                for (int off = 16; off; off >>= 1)
                    part += __shfl_xor_sync(0xffffffffu, part, off);
                run += part;
                if (has2) break;
                base -= 32;
            }
            if (lane == 0) atomicExch(&g_pk[b], ((run + S_b) << 2) | 2);
        }
        if (lane == 0) s_base = run;
    }
    __syncthreads();
    int base = s_base;
    if (i < NN) {
        g_rowptr[i + 1] = base + incl;
        g_cur[i]        = base + incl - v;
        g_dinv[i]       = rsqrtf(g_deg[i]);
    }
    if (i == 0) g_rowptr[0] = 0;
}

// ---------------- gather core: y = A' @ hin row for dest n (warp-collective) ----------------
__device__ __forceinline__ void gather_row(const float* __restrict__ hin, int n,
                                           int lane, int j0,
                                           float4& acc, float& rsum) {
    int beg = g_rowptr[n], end = g_rowptr[n + 1];
    float4 a0 = make_float4(0.f, 0.f, 0.f, 0.f);
    float4 a1 = make_float4(0.f, 0.f, 0.f, 0.f);
    float4 a2 = make_float4(0.f, 0.f, 0.f, 0.f);
    float4 a3 = make_float4(0.f, 0.f, 0.f, 0.f);
    float rsl = 0.f;
    for (int eb = beg; eb < end; eb += 32) {
        int rem = end - eb;
        int cnt = rem < 32 ? rem : 32;
        int sl = n; float wl = 0.f;
        if (lane < cnt) { sl = g_csr_src[eb + lane]; wl = g_csr_norm[eb + lane]; }
        rsl += wl;
        int cnt4 = (cnt + 3) & ~3;
        for (int i = 0; i < cnt4; i += 4) {
            int   s0 = __shfl_sync(0xffffffffu, sl, i);
            int   s1 = __shfl_sync(0xffffffffu, sl, i + 1);
            int   s2 = __shfl_sync(0xffffffffu, sl, i + 2);
            int   s3 = __shfl_sync(0xffffffffu, sl, i + 3);
            float w0 = __shfl_sync(0xffffffffu, wl, i);
            float w1 = __shfl_sync(0xffffffffu, wl, i + 1);
            float w2 = __shfl_sync(0xffffffffu, wl, i + 2);
            float w3 = __shfl_sync(0xffffffffu, wl, i + 3);
            float4 v0 = __ldg((const float4*)(hin + (size_t)s0 * 128 + j0));
            float4 v1 = __ldg((const float4*)(hin + (size_t)s1 * 128 + j0));
            float4 v2 = __ldg((const float4*)(hin + (size_t)s2 * 128 + j0));
            float4 v3 = __ldg((const float4*)(hin + (size_t)s3 * 128 + j0));
            a0.x = fmaf(w0, v0.x, a0.x); a0.y = fmaf(w0, v0.y, a0.y);
            a0.z = fmaf(w0, v0.z, a0.z); a0.w = fmaf(w0, v0.w, a0.w);
            a1.x = fmaf(w1, v1.x, a1.x); a1.y = fmaf(w1, v1.y, a1.y);
            a1.z = fmaf(w1, v1.z, a1.z); a1.w = fmaf(w1, v1.w, a1.w);
            a2.x = fmaf(w2, v2.x, a2.x); a2.y = fmaf(w2, v2.y, a2.y);
            a2.z = fmaf(w2, v2.z, a2.z); a2.w = fmaf(w2, v2.w, a2.w);
            a3.x = fmaf(w3, v3.x, a3.x); a3.y = fmaf(w3, v3.y, a3.y);
            a3.z = fmaf(w3, v3.z, a3.z); a3.w = fmaf(w3, v3.w, a3.w);
        }
    }
    float rs = rsl;
    #pragma unroll
    for (int off = 16; off; off >>= 1) rs += __shfl_xor_sync(0xffffffffu, rs, off);
    float di = g_dinv[n];
    float ws = di * di;
    float4 v = *(const float4*)(hin + (size_t)n * 128 + j0);
    acc.x = (a0.x + a1.x) + (a2.x + a3.x) + ws * v.x;
    acc.y = (a0.y + a1.y) + (a2.y + a3.y) + ws * v.y;
    acc.z = (a0.z + a1.z) + (a2.z + a3.z) + ws * v.z;
    acc.w = (a0.w + a1.w) + (a2.w + a3.w) + ws * v.w;
    rsum = rs + ws;
}

// ---------------- layer-1 aggregation: z1 = relu(A'@g_buf1 + b1), BN1 stats ----------------
__global__ __launch_bounds__(256) void k_agg1(const float* __restrict__ bias) {
    __shared__ float sred[128];
    const int tid = threadIdx.x;
    const int lane = tid & 31;
    const int gw = (blockIdx.x * blockDim.x + tid) >> 5;
    const int nw = (gridDim.x * blockDim.x) >> 5;
    const int j0 = lane * 4;
    const int ch = j0 & 63;
    const float* __restrict__ hin = g_buf1;
    float* __restrict__ hout = g_buf2;

    for (int i = tid; i < 128; i += blockDim.x) sred[i] = 0.f;
    __syncthreads();

    float4 bv = *(const float4*)(bias + ch);
    float4 ps = make_float4(0.f, 0.f, 0.f, 0.f);
    float4 pq = make_float4(0.f, 0.f, 0.f, 0.f);

    for (int n = gw; n < NN; n += nw) {
        float4 y; float rs;
        gather_row(hin, n, lane, j0, y, rs);
        float4 r;
        r.x = fmaxf(y.x + bv.x, 0.f);
        r.y = fmaxf(y.y + bv.y, 0.f);
        r.z = fmaxf(y.z + bv.z, 0.f);
        r.w = fmaxf(y.w + bv.w, 0.f);
        *(float4*)(hout + (size_t)n * 128 + j0) = r;
        ps.x += r.x; ps.y += r.y; ps.z += r.z; ps.w += r.w;
        pq.x = fmaf(r.x, r.x, pq.x); pq.y = fmaf(r.y, r.y, pq.y);
        pq.z = fmaf(r.z, r.z, pq.z); pq.w = fmaf(r.w, r.w, pq.w);
    }
    atomicAdd(&sred[ch + 0], ps.x); atomicAdd(&sred[ch + 1], ps.y);
    atomicAdd(&sred[ch + 2], ps.z); atomicAdd(&sred[ch + 3], ps.w);
    atomicAdd(&sred[64 + ch + 0], pq.x); atomicAdd(&sred[64 + ch + 1], pq.y);
    atomicAdd(&sred[64 + ch + 2], pq.z); atomicAdd(&sred[64 + ch + 3], pq.w);
    __syncthreads();
    if (tid < 128) {
        float val = sred[tid];
        if (val != 0.f) atomicAdd(&g_bn[tid], val);
    }
}

// ---------------- fold BN1 into W2 ----------------
__global__ void k_bnfold1(const float* __restrict__ g1, const float* __restrict__ be1,
                          const float* __restrict__ W2) {
    __shared__ float ss[64], st[64];
    int k = threadIdx.x;  // 64 threads
    const float inv = 1.0f / (float)MROWS;
    float m = g_bn[k] * inv;
    float v = g_bn[64 + k] * inv - m * m;
    float s = g1[k] * rsqrtf(v + EPS_BN);
    float t = fmaf(-m, s, be1[k]);
    ss[k] = s; st[k] = t;
    __syncthreads();
    float c = 0.f;
    for (int r = 0; r < 64; r++) {
        float w = W2[r * 64 + k];
        c = fmaf(st[r], w, c);
        g_W2p[r * 64 + k] = ss[r] * w;
    }
    g_c2[k] = c;
}

// ---------------- fused layer 2: y=A'@z1, h2=relu(y@W2s + rs*c2 + b2), BN2 stats ----------------
// Writes h2 into g_buf1.
__global__ __launch_bounds__(256) void k_agg2f(const float* __restrict__ bias) {
    __shared__ __align__(16) float sW2[64 * 64];   // 16KB, row-major [k][j]
    __shared__ float sred[128];
    __shared__ __align__(16) float ywarp[8][128];
    const int tid = threadIdx.x;
    const int lane = tid & 31;
    const int wid = tid >> 5;
    const int gw = (blockIdx.x * blockDim.x + tid) >> 5;
    const int nw = (gridDim.x * blockDim.x) >> 5;
    const int j0 = lane * 4;
    const int ch = j0 & 63;
    const float* __restrict__ hin = g_buf2;
    float* __restrict__ hout = g_buf1;

    for (int i = tid; i < 128; i += blockDim.x) sred[i] = 0.f;
    {
        const float4* src = (const float4*)g_W2p;
        float4* dst = (float4*)sW2;
        for (int i = tid; i < 1024; i += 256) dst[i] = src[i];
    }
    __syncthreads();

    float4 bv  = *(const float4*)(bias + ch);
    float4 c2v = *(const float4*)(g_c2 + ch);
    float4 ps = make_float4(0.f, 0.f, 0.f, 0.f);
    float4 pq = make_float4(0.f, 0.f, 0.f, 0.f);

    for (int n = gw; n < NN; n += nw) {
        float4 y; float rs;
        gather_row(hin, n, lane, j0, y, rs);

        // stage y into per-warp smem, then each lane does 4 output channels
        ywarp[wid][j0 + 0] = y.x; ywarp[wid][j0 + 1] = y.y;
        ywarp[wid][j0 + 2] = y.z; ywarp[wid][j0 + 3] = y.w;
        __syncwarp();
        const float* yb = &ywarp[wid][j0 & 64];   // batch base: 0 or 64
        float4 o = make_float4(0.f, 0.f, 0.f, 0.f);
        #pragma unroll 8
        for (int k = 0; k < 64; k++) {
            float yk = yb[k];
            float4 wr = *(const float4*)&sW2[k * 64 + ch];
            o.x = fmaf(yk, wr.x, o.x); o.y = fmaf(yk, wr.y, o.y);
            o.z = fmaf(yk, wr.z, o.z); o.w = fmaf(yk, wr.w, o.w);
        }
        __syncwarp();

        float4 r;
        r.x = fmaxf(o.x + fmaf(rs, c2v.x, bv.x), 0.f);
        r.y = fmaxf(o.y + fmaf(rs, c2v.y, bv.y), 0.f);
        r.z = fmaxf(o.z + fmaf(rs, c2v.z, bv.z), 0.f);
        r.w = fmaxf(o.w + fmaf(rs, c2v.w, bv.w), 0.f);
        *(float4*)(hout + (size_t)n * 128 + j0) = r;
        ps.x += r.x; ps.y += r.y; ps.z += r.z; ps.w += r.w;
        pq.x = fmaf(r.x, r.x, pq.x); pq.y = fmaf(r.y, r.y, pq.y);
        pq.z = fmaf(r.z, r.z, pq.z); pq.w = fmaf(r.w, r.w, pq.w);
    }
    atomicAdd(&sred[ch + 0], ps.x); atomicAdd(&sred[ch + 1], ps.y);
    atomicAdd(&sred[ch + 2], ps.z); atomicAdd(&sred[ch + 3], ps.w);
    atomicAdd(&sred[64 + ch + 0], pq.x); atomicAdd(&sred[64 + ch + 1], pq.y);
    atomicAdd(&sred[64 + ch + 2], pq.z); atomicAdd(&sred[64 + ch + 3], pq.w);
    __syncthreads();
    if (tid < 128) {
        float val = sred[tid];
        if (val != 0.f) atomicAdd(&g_bn[128 + tid], val);
    }
}

// ---------------- classifier with inline BN2 fold (reads h2 from g_buf1) ----------------
__global__ __launch_bounds__(256) void k_cls(const float* __restrict__ g2,
                                             const float* __restrict__ be2,
                                             const float* __restrict__ Wc,
                                             const float* __restrict__ bc,
                                             float* __restrict__ out) {
    __shared__ __align__(16) float swc[64];
    __shared__ float red[64];
    __shared__ float scc_s;
    const int tid = threadIdx.x;
    if (tid < 64) {
        const float inv = 1.0f / (float)MROWS;
        float m = g_bn[128 + tid] * inv;
        float v = g_bn[192 + tid] * inv - m * m;
        float s = g2[tid] * rsqrtf(v + EPS_BN);
        float t = fmaf(-m, s, be2[tid]);
        float wc = Wc[tid];
        swc[tid] = s * wc;
        red[tid] = t * wc;
    }
    __syncthreads();
    if (tid == 0) {
        float c = 0.f;
        for (int k = 0; k < 64; k++) c += red[k];
        scc_s = c + bc[0];
    }
    __syncthreads();

    const int lane = tid & 31;
    const int gw = (blockIdx.x * blockDim.x + tid) >> 5;
    const int nw = (gridDim.x * blockDim.x) >> 5;
    const int j0 = lane * 4;
    float4 wv = *(const float4*)&swc[j0 & 63];
    float cc = scc_s;
    for (int n = gw; n < NN; n += nw) {
        float4 v = *(const float4*)(g_buf1 + (size_t)n * 128 + j0);
        float d = v.x * wv.x + v.y * wv.y + v.z * wv.z + v.w * wv.w;
        d += __shfl_down_sync(0xffffffffu, d, 8, 16);
        d += __shfl_down_sync(0xffffffffu, d, 4, 16);
        d += __shfl_down_sync(0xffffffffu, d, 2, 16);
        d += __shfl_down_sync(0xffffffffu, d, 1, 16);
        if (lane == 0)  out[n]      = d + cc;
        if (lane == 16) out[NN + n] = d + cc;
    }
}

// ---------------- launcher ----------------
extern "C" void kernel_launch(void* const* d_in, const int* in_sizes, int n_in,
                              void* d_out, int out_size) {
    (void)in_sizes; (void)n_in; (void)out_size;
    const float* x    = (const float*)d_in[0];
    const float* ew   = (const float*)d_in[1];
    const float* W1   = (const float*)d_in[2];
    const float* b1   = (const float*)d_in[3];
    const float* W2   = (const float*)d_in[4];
    const float* b2   = (const float*)d_in[5];
    const float* g1   = (const float*)d_in[6];
    const float* be1  = (const float*)d_in[7];
    const float* g2   = (const float*)d_in[8];
    const float* be2  = (const float*)d_in[9];
    const float* Wc   = (const float*)d_in[10];
    const float* bc   = (const float*)d_in[11];
    const void*  eidx = d_in[12];
    float* out = (float*)d_out;

    k_init<<<196, 256>>>((const int*)eidx);
    k_fat1<<<GB2 + EB, 256>>>(x, W1, eidx, ew);           // gemm1 first half ∥ degree
    k_scan1<<<SCAN_NB, 256>>>();                          // single-pass lookback scan
    k_fat2<<<(GB - GB2) + EB, 256>>>(x, W1, eidx);        // gemm1 second half ∥ CSR fill
    k_agg1<<<2048, 256>>>(b1);                            // z1 + BN1 stats
    k_bnfold1<<<1, 64>>>(g1, be1, W2);                    // W2s, c2
    k_agg2f<<<2048, 256>>>(b2);                           // fused agg + 64x64 GEMM + BN2 stats
    k_cls<<<1024, 256>>>(g2, be2, Wc, bc, out);           // BN2 fold inlined
}